// round 6
// baseline (speedup 1.0000x reference)
#include <cuda_runtime.h>
#include <cuda_bf16.h>
#include <cstdint>
#include <math.h>

// ===================== problem constants =====================
#define D 128
#define NROWS (64 * 4096)          // B*T = 262144
#define NTILES (NROWS / 128)       // 2048
#define GRID_MAIN 148
#define NTHREADS 256               // 8 warps; each warp owns 16 rows of the 128-row tile

// ===================== device scratch (no allocations allowed) =====================
__device__ float g_T1[D * D];
__device__ float g_bg[D];
__device__ float g_W1[D * D];
__device__ float g_b1[D];

// ===================== precompute kernels (fold the linear prefix) =====================
// T1 = graph @ W_upd[128:], bg = b_msg @ graph
__global__ void pre1(const float* __restrict__ graph, const float* __restrict__ W_upd,
                     const float* __restrict__ b_msg) {
    int j = threadIdx.x;
    int i = blockIdx.x;
    if (i < D) {
        float acc = 0.f;
#pragma unroll 8
        for (int g = 0; g < D; g++)
            acc += graph[i * D + g] * W_upd[(D + g) * D + j];
        g_T1[i * D + j] = acc;
    } else {
        float acc = 0.f;
#pragma unroll 8
        for (int g = 0; g < D; g++)
            acc += b_msg[g] * graph[g * D + j];
        g_bg[j] = acc;
    }
}
// W1 = W_upd[:128] + W_msg @ T1, b1 = b_upd + bg @ W_upd[128:]
__global__ void pre2(const float* __restrict__ W_msg, const float* __restrict__ W_upd,
                     const float* __restrict__ b_upd) {
    int j = threadIdx.x;
    int i = blockIdx.x;
    if (i < D) {
        float acc = W_upd[i * D + j];
#pragma unroll 8
        for (int h = 0; h < D; h++)
            acc += W_msg[i * D + h] * g_T1[h * D + j];
        g_W1[i * D + j] = acc;
    } else {
        float acc = b_upd[j];
#pragma unroll 8
        for (int h = 0; h < D; h++)
            acc += g_bg[h] * W_upd[(D + h) * D + j];
        g_b1[j] = acc;
    }
}

// ===================== helpers =====================
__device__ __forceinline__ uint32_t smem_u32(const void* p) {
    uint32_t a;
    asm("{ .reg .u64 t; cvta.to.shared.u64 t, %1; cvt.u32.u64 %0, t; }" : "=r"(a) : "l"(p));
    return a;
}
__device__ __forceinline__ uint32_t pack2(__nv_bfloat16 a, __nv_bfloat16 b) {
    return (uint32_t)__bfloat16_as_ushort(a) | ((uint32_t)__bfloat16_as_ushort(b) << 16);
}
__device__ __forceinline__ void split2(float x0, float x1, uint32_t& hi, uint32_t& lo) {
    __nv_bfloat16 h0 = __float2bfloat16(x0), h1 = __float2bfloat16(x1);
    hi = pack2(h0, h1);
    lo = pack2(__float2bfloat16(x0 - __bfloat162float(h0)),
               __float2bfloat16(x1 - __bfloat162float(h1)));
}
__device__ __forceinline__ float gelu_exact(float v) {
    return 0.5f * v * (1.0f + erff(v * 0.70710678118654752f));
}

// mma.sync m16n8k16 bf16 -> f32, accumulate in place
#define MMA(c0, c1, c2, c3, a0, a1, a2, a3, b0, b1)                                   \
    asm volatile("mma.sync.aligned.m16n8k16.row.col.f32.bf16.bf16.f32 "               \
                 "{%0,%1,%2,%3}, {%4,%5,%6,%7}, {%8,%9}, {%0,%1,%2,%3};"              \
                 : "+f"(c0), "+f"(c1), "+f"(c2), "+f"(c3)                             \
                 : "r"(a0), "r"(a1), "r"(a2), "r"(a3), "r"(b0), "r"(b1))

// ldmatrix x4 non-trans: regs r0..r3 <- matrices addressed by lane groups 0-7/8-15/16-23/24-31
#define LDSM4(r0, r1, r2, r3, addr)                                                    \
    asm volatile("ldmatrix.sync.aligned.m8n8.x4.shared.b16 {%0,%1,%2,%3}, [%4];"       \
                 : "=r"(r0), "=r"(r1), "=r"(r2), "=r"(r3) : "r"(addr))

// ===================== SMEM map =====================
// Weight images: [n][k] bf16, 256B rows, XOR-swizzled 16B chunks (conflict-free ldmatrix)
#define SW1H 0
#define SW1L 32768
#define SW2H 65536
#define SW2L 98304
#define SB1  131072
#define SB2  131584
#define SGAM 132096
#define SBET 132608
#define SMEM_BYTES 133120

// Inner j-loop: one k-step (16) of a 16x128 * 128x128 warp-GEMM, 3-term hi/lo
__device__ __forceinline__ void gemm_kstep(float (&c)[16][4],
                                           const uint32_t* aH, const uint32_t* aL,
                                           uint32_t baseH, uint32_t baseL, uint32_t sAdd) {
#pragma unroll
    for (int j = 0; j < 8; j++) {
        uint32_t bh0, bh1, bh2, bh3, bl0, bl1, bl2, bl3;
        LDSM4(bh0, bh1, bh2, bh3, baseH + j * 4096 + sAdd);
        LDSM4(bl0, bl1, bl2, bl3, baseL + j * 4096 + sAdd);
        // nblk 2j: B frag {r0,r1}; nblk 2j+1: {r2,r3}
        MMA(c[2 * j][0], c[2 * j][1], c[2 * j][2], c[2 * j][3],
            aH[0], aH[1], aH[2], aH[3], bh0, bh1);
        MMA(c[2 * j][0], c[2 * j][1], c[2 * j][2], c[2 * j][3],
            aH[0], aH[1], aH[2], aH[3], bl0, bl1);
        MMA(c[2 * j][0], c[2 * j][1], c[2 * j][2], c[2 * j][3],
            aL[0], aL[1], aL[2], aL[3], bh0, bh1);
        MMA(c[2 * j + 1][0], c[2 * j + 1][1], c[2 * j + 1][2], c[2 * j + 1][3],
            aH[0], aH[1], aH[2], aH[3], bh2, bh3);
        MMA(c[2 * j + 1][0], c[2 * j + 1][1], c[2 * j + 1][2], c[2 * j + 1][3],
            aH[0], aH[1], aH[2], aH[3], bl2, bl3);
        MMA(c[2 * j + 1][0], c[2 * j + 1][1], c[2 * j + 1][2], c[2 * j + 1][3],
            aL[0], aL[1], aL[2], aL[3], bh2, bh3);
    }
}

// ===================== main fused kernel =====================
__global__ void __launch_bounds__(NTHREADS, 1)
lgn_main(const float* __restrict__ x, const float* __restrict__ Wout,
         const float* __restrict__ bout, const float* __restrict__ gamma,
         const float* __restrict__ beta, float* __restrict__ out) {
    extern __shared__ char smem[];
    const uint32_t sb = smem_u32(smem);
    const int tid = threadIdx.x;
    const int wid = tid >> 5;
    const int l = tid & 31;
    const int quad = l >> 2;       // fragment row within 8
    const int qid = l & 3;         // fragment col pair selector
    const int warpRow = wid * 16;  // rows [warpRow, warpRow+16) of the 128-row tile

    // ---- one-time weight staging: hi/lo bf16, [n][k] layout, XOR swizzle ----
    for (int idx = tid; idx < D * D; idx += NTHREADS) {
        int n = idx >> 7, k = idx & 127;
        uint32_t off = (uint32_t)(n * 256 + k * 2);
        uint32_t swz = off ^ ((uint32_t)(n & 7) << 4);
        float w1 = g_W1[k * D + n];
        __nv_bfloat16 h1 = __float2bfloat16(w1);
        *(__nv_bfloat16*)(smem + SW1H + swz) = h1;
        *(__nv_bfloat16*)(smem + SW1L + swz) = __float2bfloat16(w1 - __bfloat162float(h1));
        float w2 = Wout[k * D + n];
        __nv_bfloat16 h2 = __float2bfloat16(w2);
        *(__nv_bfloat16*)(smem + SW2H + swz) = h2;
        *(__nv_bfloat16*)(smem + SW2L + swz) = __float2bfloat16(w2 - __bfloat162float(h2));
    }
    if (tid < D) {
        ((float*)(smem + SB1))[tid]  = g_b1[tid];
        ((float*)(smem + SB2))[tid]  = bout[tid];
        ((float*)(smem + SGAM))[tid] = gamma[tid];
        ((float*)(smem + SBET))[tid] = beta[tid];
    }
    __syncthreads();

    const float* b1s = (const float*)(smem + SB1);
    const float* b2s = (const float*)(smem + SB2);
    const float* gms = (const float*)(smem + SGAM);
    const float* bts = (const float*)(smem + SBET);

    // per-lane ldmatrix address pieces (constant across tiles)
    const uint32_t nlane = ((l >> 4) & 1) * 8 + (l & 7);   // n row within 16-block
    const uint32_t laneN = nlane * 256;
    const uint32_t xorv  = (nlane & 7) << 4;
    const uint32_t kl2   = ((l >> 3) & 1) * 16;            // byte offset for k half (+8 elems)

    for (int t = blockIdx.x; t < NTILES; t += gridDim.x) {
        const float* xrow = x + (size_t)t * (128 * D) + (warpRow + quad) * D + qid * 2;

        // ================= GEMM1: C1 = x @ W1 + b1 =================
        float c1[16][4];
#pragma unroll
        for (int j = 0; j < 16; j++) {
            float2 bb = *(const float2*)(b1s + 8 * j + qid * 2);
            c1[j][0] = bb.x; c1[j][1] = bb.y; c1[j][2] = bb.x; c1[j][3] = bb.y;
        }
#pragma unroll
        for (int s = 0; s < 8; s++) {
            float2 v00 = *(const float2*)(xrow + 16 * s);
            float2 v10 = *(const float2*)(xrow + 16 * s + 8 * D);
            float2 v01 = *(const float2*)(xrow + 16 * s + 8);
            float2 v11 = *(const float2*)(xrow + 16 * s + 8 * D + 8);
            uint32_t aH[4], aL[4];
            split2(v00.x, v00.y, aH[0], aL[0]);
            split2(v10.x, v10.y, aH[1], aL[1]);
            split2(v01.x, v01.y, aH[2], aL[2]);
            split2(v11.x, v11.y, aH[3], aL[3]);
            uint32_t sAdd = laneN + (((uint32_t)(32 * s) + kl2) ^ xorv);
            gemm_kstep(c1, aH, aL, sb + SW1H, sb + SW1L, sAdd);
        }

        // ================= epilogue 1: exact GELU, split -> A frags for GEMM2 =================
        uint32_t a2h[32], a2l[32];
#pragma unroll
        for (int j = 0; j < 16; j++) {
#pragma unroll
            for (int p = 0; p < 2; p++) {
                float v0 = gelu_exact(c1[j][2 * p]);
                float v1 = gelu_exact(c1[j][2 * p + 1]);
                split2(v0, v1, a2h[2 * j + p], a2l[2 * j + p]);
            }
        }

        // ================= GEMM2: C2 = h @ W_out + b_out =================
        float c2[16][4];
#pragma unroll
        for (int j = 0; j < 16; j++) {
            float2 bb = *(const float2*)(b2s + 8 * j + qid * 2);
            c2[j][0] = bb.x; c2[j][1] = bb.y; c2[j][2] = bb.x; c2[j][3] = bb.y;
        }
#pragma unroll
        for (int s = 0; s < 8; s++) {
            uint32_t sAdd = laneN + (((uint32_t)(32 * s) + kl2) ^ xorv);
            gemm_kstep(c2, &a2h[4 * s], &a2l[4 * s], sb + SW2H, sb + SW2L, sAdd);
        }

        // ================= epilogue 2: LayerNorm + store =================
        float sA = 0.f, qA = 0.f, sB = 0.f, qB = 0.f;
#pragma unroll
        for (int j = 0; j < 16; j++) {
            sA += c2[j][0] + c2[j][1];
            qA += c2[j][0] * c2[j][0] + c2[j][1] * c2[j][1];
            sB += c2[j][2] + c2[j][3];
            qB += c2[j][2] * c2[j][2] + c2[j][3] * c2[j][3];
        }
#pragma unroll
        for (int m = 1; m < 4; m <<= 1) {
            sA += __shfl_xor_sync(0xFFFFFFFFu, sA, m);
            qA += __shfl_xor_sync(0xFFFFFFFFu, qA, m);
            sB += __shfl_xor_sync(0xFFFFFFFFu, sB, m);
            qB += __shfl_xor_sync(0xFFFFFFFFu, qB, m);
        }
        float mA = sA * (1.0f / 128.0f);
        float vA = qA * (1.0f / 128.0f) - mA * mA;
        float iA = rsqrtf(vA + 1e-5f);
        float mB = sB * (1.0f / 128.0f);
        float vB = qB * (1.0f / 128.0f) - mB * mB;
        float iB = rsqrtf(vB + 1e-5f);

        float* orow = out + (size_t)t * (128 * D) + (warpRow + quad) * D + qid * 2;
#pragma unroll
        for (int j = 0; j < 16; j++) {
            float2 g = *(const float2*)(gms + 8 * j + qid * 2);
            float2 b = *(const float2*)(bts + 8 * j + qid * 2);
            float2 oA, oB;
            oA.x = (c2[j][0] - mA) * iA * g.x + b.x;
            oA.y = (c2[j][1] - mA) * iA * g.y + b.y;
            oB.x = (c2[j][2] - mB) * iB * g.x + b.x;
            oB.y = (c2[j][3] - mB) * iB * g.y + b.y;
            *(float2*)(orow + 8 * j) = oA;
            *(float2*)(orow + 8 * j + 8 * D) = oB;
        }
    }
}

// ===================== launch =====================
extern "C" void kernel_launch(void* const* d_in, const int* in_sizes, int n_in,
                              void* d_out, int out_size) {
    const float* x     = (const float*)d_in[0];
    const float* graph = (const float*)d_in[1];
    const float* W_msg = (const float*)d_in[2];
    const float* b_msg = (const float*)d_in[3];
    const float* W_upd = (const float*)d_in[4];
    const float* b_upd = (const float*)d_in[5];
    const float* W_out = (const float*)d_in[6];
    const float* b_out = (const float*)d_in[7];
    const float* gamma = (const float*)d_in[8];
    const float* beta  = (const float*)d_in[9];
    float* out = (float*)d_out;

    static int configured = 0;
    cudaFuncSetAttribute(lgn_main, cudaFuncAttributeMaxDynamicSharedMemorySize, SMEM_BYTES);
    (void)configured;

    pre1<<<129, 128>>>(graph, W_upd, b_msg);
    pre2<<<129, 128>>>(W_msg, W_upd, b_upd);
    lgn_main<<<GRID_MAIN, NTHREADS, SMEM_BYTES>>>(x, W_out, b_out, gamma, beta, out);
}

// round 9
// speedup vs baseline: 1.0421x; 1.0421x over previous
#include <cuda_runtime.h>
#include <cuda_bf16.h>
#include <cstdint>
#include <math.h>

// ===================== problem constants =====================
#define D 128
#define NROWS (64 * 4096)          // B*T = 262144
#define NTILES (NROWS / 128)       // 2048
#define GRID_MAIN 148
#define NTHREADS 256               // 8 warps; each warp owns 16 rows of a 128-row tile

// ===================== helpers =====================
__device__ __forceinline__ uint32_t smem_u32(const void* p) {
    uint32_t a;
    asm("{ .reg .u64 t; cvta.to.shared.u64 t, %1; cvt.u32.u64 %0, t; }" : "=r"(a) : "l"(p));
    return a;
}
__device__ __forceinline__ uint32_t pack2(__nv_bfloat16 a, __nv_bfloat16 b) {
    return (uint32_t)__bfloat16_as_ushort(a) | ((uint32_t)__bfloat16_as_ushort(b) << 16);
}
__device__ __forceinline__ void split2(float x0, float x1, uint32_t& hi, uint32_t& lo) {
    __nv_bfloat16 h0 = __float2bfloat16(x0), h1 = __float2bfloat16(x1);
    hi = pack2(h0, h1);
    lo = pack2(__float2bfloat16(x0 - __bfloat162float(h0)),
               __float2bfloat16(x1 - __bfloat162float(h1)));
}
__device__ __forceinline__ float gelu_exact(float v) {
    return 0.5f * v * (1.0f + erff(v * 0.70710678118654752f));
}

// mma.sync m16n8k16 bf16 -> f32, accumulate in place
#define MMA(c0, c1, c2, c3, a0, a1, a2, a3, b0, b1)                                   \
    asm volatile("mma.sync.aligned.m16n8k16.row.col.f32.bf16.bf16.f32 "               \
                 "{%0,%1,%2,%3}, {%4,%5,%6,%7}, {%8,%9}, {%0,%1,%2,%3};"              \
                 : "+f"(c0), "+f"(c1), "+f"(c2), "+f"(c3)                             \
                 : "r"(a0), "r"(a1), "r"(a2), "r"(a3), "r"(b0), "r"(b1))

#define LDSM4(r0, r1, r2, r3, addr)                                                    \
    asm volatile("ldmatrix.sync.aligned.m8n8.x4.shared.b16 {%0,%1,%2,%3}, [%4];"       \
                 : "=r"(r0), "=r"(r1), "=r"(r2), "=r"(r3) : "r"(addr))

// ===================== SMEM map =====================
// Weight images: [n][k] bf16, 256B rows, XOR-swizzled 16B chunks (conflict-free ldmatrix)
#define SW1H 0
#define SW1L 32768
#define SW2H 65536
#define SW2L 98304
#define SB1  131072     // b1 (also 1024B scratch spanning SB1+SB2 during precompute)
#define SB2  131584     // b_out
#define SGAM 132096     // gamma (bg vector during precompute)
#define SBET 132608     // beta
#define SMEM_BYTES 133120

// Inner k-step (K=16) of a 16x128 * 128x128 warp-GEMM, 3-term hi/lo.
// MMAs ordered to alternate accumulators (max same-acc chain distance 2).
__device__ __forceinline__ void gemm_kstep(float (&c)[16][4],
                                           const uint32_t* aH, const uint32_t* aL,
                                           uint32_t baseH, uint32_t baseL, uint32_t sAdd) {
#pragma unroll
    for (int j = 0; j < 8; j++) {
        uint32_t bh0, bh1, bh2, bh3, bl0, bl1, bl2, bl3;
        LDSM4(bh0, bh1, bh2, bh3, baseH + j * 4096 + sAdd);
        LDSM4(bl0, bl1, bl2, bl3, baseL + j * 4096 + sAdd);
        MMA(c[2 * j][0], c[2 * j][1], c[2 * j][2], c[2 * j][3],
            aH[0], aH[1], aH[2], aH[3], bh0, bh1);
        MMA(c[2 * j + 1][0], c[2 * j + 1][1], c[2 * j + 1][2], c[2 * j + 1][3],
            aH[0], aH[1], aH[2], aH[3], bh2, bh3);
        MMA(c[2 * j][0], c[2 * j][1], c[2 * j][2], c[2 * j][3],
            aH[0], aH[1], aH[2], aH[3], bl0, bl1);
        MMA(c[2 * j + 1][0], c[2 * j + 1][1], c[2 * j + 1][2], c[2 * j + 1][3],
            aH[0], aH[1], aH[2], aH[3], bl2, bl3);
        MMA(c[2 * j][0], c[2 * j][1], c[2 * j][2], c[2 * j][3],
            aL[0], aL[1], aL[2], aL[3], bh0, bh1);
        MMA(c[2 * j + 1][0], c[2 * j + 1][1], c[2 * j + 1][2], c[2 * j + 1][3],
            aL[0], aL[1], aL[2], aL[3], bh2, bh3);
    }
}

// Store one fp32 value into a hi/lo bf16 B-image ([n][k] layout, XOR swizzle) at (k=m, n).
__device__ __forceinline__ void store_bimg(char* smem, uint32_t dH, uint32_t dL,
                                           int m, int n, float v) {
    uint32_t off = ((uint32_t)(n * 256 + m * 2)) ^ (((uint32_t)n & 7u) << 4);
    __nv_bfloat16 h = __float2bfloat16(v);
    *(__nv_bfloat16*)(smem + dH + off) = h;
    *(__nv_bfloat16*)(smem + dL + off) = __float2bfloat16(v - __bfloat162float(h));
}

// ===================== single fused kernel =====================
__global__ void __launch_bounds__(NTHREADS, 1)
lgn_main(const float* __restrict__ x, const float* __restrict__ graph,
         const float* __restrict__ W_msg, const float* __restrict__ b_msg,
         const float* __restrict__ W_upd, const float* __restrict__ b_upd,
         const float* __restrict__ Wout, const float* __restrict__ bout,
         const float* __restrict__ gamma, const float* __restrict__ beta,
         float* __restrict__ out) {
    extern __shared__ char smem[];
    const uint32_t sb = smem_u32(smem);
    const int tid = threadIdx.x;
    const int wid = tid >> 5;
    const int l = tid & 31;
    const int quad = l >> 2;       // fragment row within 8
    const int qid = l & 3;         // fragment col pair selector
    const int warpRow = wid * 16;  // rows [warpRow, warpRow+16)

    // per-lane ldmatrix address pieces (constant throughout)
    const uint32_t nlane = ((l >> 4) & 1) * 8 + (l & 7);
    const uint32_t laneN = nlane * 256;
    const uint32_t xorv  = (nlane & 7) << 4;
    const uint32_t kl2   = ((l >> 3) & 1) * 16;

    const int mA = warpRow + quad;
    const int mB = mA + 8;

    // =========================================================================
    // In-kernel precompute (per-CTA, redundant but concurrent across CTAs):
    //   T1 = graph @ W_upd[128:],  W1 = W_upd[:128] + W_msg @ T1
    //   bg = b_msg @ graph,        b1 = b_upd + bg @ W_upd[128:]
    // =========================================================================

    // ---- P0: stage Wb = W_upd[128:] as B image into SW1; bg partial sums ----
    for (int idx = tid; idx < D * D; idx += NTHREADS) {
        int k = idx >> 7, n = idx & 127;
        float w = W_upd[(D + k) * D + n];
        store_bimg(smem, SW1H, SW1L, k, n, w);
    }
    {
        int j = tid & 127, hh = tid >> 7;
        float p = 0.f;
#pragma unroll 8
        for (int g = hh * 64; g < hh * 64 + 64; g++)
            p += b_msg[g] * graph[g * D + j];
        ((float*)(smem + SB1))[tid] = p;   // 256 floats spanning SB1+SB2
    }
    __syncthreads();
    if (tid < D) {
        float bg = ((float*)(smem + SB1))[tid] + ((float*)(smem + SB1))[tid + 128];
        ((float*)(smem + SGAM))[tid] = bg;   // park bg in SGAM for now
    }

    // ---- P1: T1 rows (warp-tiled) = graph @ Wb ; write T1^T -> SW2 B-image ----
    {
        float c[16][4];
#pragma unroll
        for (int j = 0; j < 16; j++) { c[j][0] = c[j][1] = c[j][2] = c[j][3] = 0.f; }
        const float* arow = graph + (size_t)mA * D + qid * 2;
#pragma unroll
        for (int s = 0; s < 8; s++) {
            float2 v00 = *(const float2*)(arow + 16 * s);
            float2 v10 = *(const float2*)(arow + 16 * s + 8 * D);
            float2 v01 = *(const float2*)(arow + 16 * s + 8);
            float2 v11 = *(const float2*)(arow + 16 * s + 8 * D + 8);
            uint32_t aH[4], aL[4];
            split2(v00.x, v00.y, aH[0], aL[0]);
            split2(v10.x, v10.y, aH[1], aL[1]);
            split2(v01.x, v01.y, aH[2], aL[2]);
            split2(v11.x, v11.y, aH[3], aL[3]);
            uint32_t sAdd = laneN + (((uint32_t)(32 * s) + kl2) ^ xorv);
            gemm_kstep(c, aH, aL, sb + SW1H, sb + SW1L, sAdd);
        }
#pragma unroll
        for (int j = 0; j < 16; j++) {
            int n0 = 8 * j + qid * 2;
            store_bimg(smem, SW2H, SW2L, mA, n0,     c[j][0]);
            store_bimg(smem, SW2H, SW2L, mA, n0 + 1, c[j][1]);
            store_bimg(smem, SW2H, SW2L, mB, n0,     c[j][2]);
            store_bimg(smem, SW2H, SW2L, mB, n0 + 1, c[j][3]);
        }
    }
    __syncthreads();

    // ---- P2: W1 rows = W_upd[:128] + W_msg @ T1 ; write -> SW1 B-image ----
    {
        float c[16][4];
#pragma unroll
        for (int j = 0; j < 16; j++) { c[j][0] = c[j][1] = c[j][2] = c[j][3] = 0.f; }
        const float* arow = W_msg + (size_t)mA * D + qid * 2;
#pragma unroll
        for (int s = 0; s < 8; s++) {
            float2 v00 = *(const float2*)(arow + 16 * s);
            float2 v10 = *(const float2*)(arow + 16 * s + 8 * D);
            float2 v01 = *(const float2*)(arow + 16 * s + 8);
            float2 v11 = *(const float2*)(arow + 16 * s + 8 * D + 8);
            uint32_t aH[4], aL[4];
            split2(v00.x, v00.y, aH[0], aL[0]);
            split2(v10.x, v10.y, aH[1], aL[1]);
            split2(v01.x, v01.y, aH[2], aL[2]);
            split2(v11.x, v11.y, aH[3], aL[3]);
            uint32_t sAdd = laneN + (((uint32_t)(32 * s) + kl2) ^ xorv);
            gemm_kstep(c, aH, aL, sb + SW2H, sb + SW2L, sAdd);
        }
#pragma unroll
        for (int j = 0; j < 16; j++) {   // += W_upd top half
            int n0 = 8 * j + qid * 2;
            float2 tA = *(const float2*)(W_upd + (size_t)mA * D + n0);
            float2 tB = *(const float2*)(W_upd + (size_t)mB * D + n0);
            c[j][0] += tA.x; c[j][1] += tA.y; c[j][2] += tB.x; c[j][3] += tB.y;
        }
        // SW1 (Wb) is dead after P1's sync -> safe to overwrite while P2 MMAs (SW2) run
#pragma unroll
        for (int j = 0; j < 16; j++) {
            int n0 = 8 * j + qid * 2;
            store_bimg(smem, SW1H, SW1L, mA, n0,     c[j][0]);
            store_bimg(smem, SW1H, SW1L, mA, n0 + 1, c[j][1]);
            store_bimg(smem, SW1H, SW1L, mB, n0,     c[j][2]);
            store_bimg(smem, SW1H, SW1L, mB, n0 + 1, c[j][3]);
        }
    }
    __syncthreads();

    // ---- P3: stage W_out -> SW2 (T1^T dead); b1 from bg; then final vectors ----
    for (int idx = tid; idx < D * D; idx += NTHREADS) {
        int k = idx >> 7, n = idx & 127;
        store_bimg(smem, SW2H, SW2L, k, n, Wout[k * D + n]);
    }
    if (tid < D) {
        const float* bgv = (const float*)(smem + SGAM);
        float acc = b_upd[tid];
#pragma unroll 8
        for (int h = 0; h < D; h++)
            acc += bgv[h] * W_upd[(D + h) * D + tid];
        ((float*)(smem + SB1))[tid] = acc;       // b1
    }
    __syncthreads();                             // b1 done reading bg before gamma overwrite
    if (tid < D) {
        ((float*)(smem + SB2))[tid]  = bout[tid];
        ((float*)(smem + SGAM))[tid] = gamma[tid];
        ((float*)(smem + SBET))[tid] = beta[tid];
    }
    __syncthreads();

    const float* b1s = (const float*)(smem + SB1);
    const float* b2s = (const float*)(smem + SB2);
    const float* gms = (const float*)(smem + SGAM);
    const float* bts = (const float*)(smem + SBET);

    // =========================================================================
    // Main loop: per 128-row tile:  y = LN( gelu(x@W1 + b1) @ W2 + b2 )
    // =========================================================================
    for (int t = blockIdx.x; t < NTILES; t += gridDim.x) {
        const float* xrow = x + (size_t)t * (128 * D) + (size_t)mA * D + qid * 2;

        // ---- GEMM1: C1 = x @ W1 + b1 ----
        float c1[16][4];
#pragma unroll
        for (int j = 0; j < 16; j++) {
            float2 bb = *(const float2*)(b1s + 8 * j + qid * 2);
            c1[j][0] = bb.x; c1[j][1] = bb.y; c1[j][2] = bb.x; c1[j][3] = bb.y;
        }
#pragma unroll
        for (int s = 0; s < 8; s++) {
            float2 v00 = *(const float2*)(xrow + 16 * s);
            float2 v10 = *(const float2*)(xrow + 16 * s + 8 * D);
            float2 v01 = *(const float2*)(xrow + 16 * s + 8);
            float2 v11 = *(const float2*)(xrow + 16 * s + 8 * D + 8);
            uint32_t aH[4], aL[4];
            split2(v00.x, v00.y, aH[0], aL[0]);
            split2(v10.x, v10.y, aH[1], aL[1]);
            split2(v01.x, v01.y, aH[2], aL[2]);
            split2(v11.x, v11.y, aH[3], aL[3]);
            uint32_t sAdd = laneN + (((uint32_t)(32 * s) + kl2) ^ xorv);
            gemm_kstep(c1, aH, aL, sb + SW1H, sb + SW1L, sAdd);
        }

        // ---- epilogue 1: exact GELU, split -> A frags for GEMM2 (reg-resident) ----
        uint32_t a2h[32], a2l[32];
#pragma unroll
        for (int j = 0; j < 16; j++) {
#pragma unroll
            for (int p = 0; p < 2; p++) {
                float v0 = gelu_exact(c1[j][2 * p]);
                float v1 = gelu_exact(c1[j][2 * p + 1]);
                split2(v0, v1, a2h[2 * j + p], a2l[2 * j + p]);
            }
        }

        // ---- GEMM2: C2 = h @ W_out + b_out ----
        float c2[16][4];
#pragma unroll
        for (int j = 0; j < 16; j++) {
            float2 bb = *(const float2*)(b2s + 8 * j + qid * 2);
            c2[j][0] = bb.x; c2[j][1] = bb.y; c2[j][2] = bb.x; c2[j][3] = bb.y;
        }
#pragma unroll
        for (int s = 0; s < 8; s++) {
            uint32_t sAdd = laneN + (((uint32_t)(32 * s) + kl2) ^ xorv);
            gemm_kstep(c2, &a2h[4 * s], &a2l[4 * s], sb + SW2H, sb + SW2L, sAdd);
        }

        // ---- epilogue 2: LayerNorm (quad bfly reduce) + store ----
        float sA = 0.f, qA = 0.f, sB = 0.f, qB = 0.f;
#pragma unroll
        for (int j = 0; j < 16; j++) {
            sA += c2[j][0] + c2[j][1];
            qA += c2[j][0] * c2[j][0] + c2[j][1] * c2[j][1];
            sB += c2[j][2] + c2[j][3];
            qB += c2[j][2] * c2[j][2] + c2[j][3] * c2[j][3];
        }
#pragma unroll
        for (int m = 1; m < 4; m <<= 1) {
            sA += __shfl_xor_sync(0xFFFFFFFFu, sA, m);
            qA += __shfl_xor_sync(0xFFFFFFFFu, qA, m);
            sB += __shfl_xor_sync(0xFFFFFFFFu, sB, m);
            qB += __shfl_xor_sync(0xFFFFFFFFu, qB, m);
        }
        float mnA = sA * (1.0f / 128.0f);
        float vA = qA * (1.0f / 128.0f) - mnA * mnA;
        float iA = rsqrtf(vA + 1e-5f);
        float mnB = sB * (1.0f / 128.0f);
        float vB = qB * (1.0f / 128.0f) - mnB * mnB;
        float iB = rsqrtf(vB + 1e-5f);

        float* orow = out + (size_t)t * (128 * D) + (size_t)mA * D + qid * 2;
#pragma unroll
        for (int j = 0; j < 16; j++) {
            float2 g = *(const float2*)(gms + 8 * j + qid * 2);
            float2 b = *(const float2*)(bts + 8 * j + qid * 2);
            float2 oA, oB;
            oA.x = (c2[j][0] - mnA) * iA * g.x + b.x;
            oA.y = (c2[j][1] - mnA) * iA * g.y + b.y;
            oB.x = (c2[j][2] - mnB) * iB * g.x + b.x;
            oB.y = (c2[j][3] - mnB) * iB * g.y + b.y;
            *(float2*)(orow + 8 * j) = oA;
            *(float2*)(orow + 8 * j + 8 * D) = oB;
        }
    }
}

// ===================== launch (single kernel per call) =====================
extern "C" void kernel_launch(void* const* d_in, const int* in_sizes, int n_in,
                              void* d_out, int out_size) {
    const float* x     = (const float*)d_in[0];
    const float* graph = (const float*)d_in[1];
    const float* W_msg = (const float*)d_in[2];
    const float* b_msg = (const float*)d_in[3];
    const float* W_upd = (const float*)d_in[4];
    const float* b_upd = (const float*)d_in[5];
    const float* W_out = (const float*)d_in[6];
    const float* b_out = (const float*)d_in[7];
    const float* gamma = (const float*)d_in[8];
    const float* beta  = (const float*)d_in[9];
    float* out = (float*)d_out;

    cudaFuncSetAttribute(lgn_main, cudaFuncAttributeMaxDynamicSharedMemorySize, SMEM_BYTES);

    lgn_main<<<GRID_MAIN, NTHREADS, SMEM_BYTES>>>(
        x, graph, W_msg, b_msg, W_upd, b_upd, W_out, b_out, gamma, beta, out);
}

// round 10
// speedup vs baseline: 1.1156x; 1.0705x over previous
#include <cuda_runtime.h>
#include <cuda_bf16.h>
#include <cstdint>
#include <math.h>

// ===================== problem constants =====================
#define D 128
#define NROWS (64 * 4096)          // B*T = 262144
#define NTILES (NROWS / 128)       // 2048
#define GRID_MAIN 148
#define NTHREADS 512               // 16 warps = 8 pairs; pair owns 16 rows, warp owns 64 cols

// ===================== helpers =====================
__device__ __forceinline__ uint32_t smem_u32(const void* p) {
    uint32_t a;
    asm("{ .reg .u64 t; cvta.to.shared.u64 t, %1; cvt.u32.u64 %0, t; }" : "=r"(a) : "l"(p));
    return a;
}
__device__ __forceinline__ uint32_t pack2(__nv_bfloat16 a, __nv_bfloat16 b) {
    return (uint32_t)__bfloat16_as_ushort(a) | ((uint32_t)__bfloat16_as_ushort(b) << 16);
}
__device__ __forceinline__ void split2(float x0, float x1, uint32_t& hi, uint32_t& lo) {
    __nv_bfloat16 h0 = __float2bfloat16(x0), h1 = __float2bfloat16(x1);
    hi = pack2(h0, h1);
    lo = pack2(__float2bfloat16(x0 - __bfloat162float(h0)),
               __float2bfloat16(x1 - __bfloat162float(h1)));
}
__device__ __forceinline__ float gelu_exact(float v) {
    return 0.5f * v * (1.0f + erff(v * 0.70710678118654752f));
}

// mma.sync m16n8k16 bf16 -> f32, accumulate in place
#define MMA(c0, c1, c2, c3, a0, a1, a2, a3, b0, b1)                                   \
    asm volatile("mma.sync.aligned.m16n8k16.row.col.f32.bf16.bf16.f32 "               \
                 "{%0,%1,%2,%3}, {%4,%5,%6,%7}, {%8,%9}, {%0,%1,%2,%3};"              \
                 : "+f"(c0), "+f"(c1), "+f"(c2), "+f"(c3)                             \
                 : "r"(a0), "r"(a1), "r"(a2), "r"(a3), "r"(b0), "r"(b1))

#define LDSM4(r0, r1, r2, r3, addr)                                                    \
    asm volatile("ldmatrix.sync.aligned.m8n8.x4.shared.b16 {%0,%1,%2,%3}, [%4];"       \
                 : "=r"(r0), "=r"(r1), "=r"(r2), "=r"(r3) : "r"(addr))

// named barrier for a 64-thread pair (ids 1..8)
#define BARP(id) asm volatile("bar.sync %0, 64;" :: "r"(id) : "memory")

// ===================== SMEM map =====================
// Weight images: [n][k] bf16, 256B rows, XOR-swizzled 16B chunks (conflict-free ldmatrix)
#define SW1H 0
#define SW1L 32768
#define SW2H 65536
#define SW2L 98304
#define SHH  131072     // h staging hi: 8 pairs * 4 KB (16 rows x 256B, A layout)
#define SHL  163840     // h staging lo
#define SB1  196608     // b1
#define SB2  197120     // b_out
#define SGAM 197632     // gamma (bg during precompute)
#define SBET 198144     // beta
#define SRED 198656     // 2 KB: LN pair partials / bg scratch
#define SMEM_BYTES 200704

// One k-step (K=16) of a 16x64 * 64<-128 half-warp GEMM, 3-term hi/lo.
// c[8][4] covers 16 rows x 64 cols (8 n-blocks). sAdd includes half*16384 + laneN + swizzled k.
__device__ __forceinline__ void pair_kstep(float (&c)[8][4],
                                           const uint32_t* aH, const uint32_t* aL,
                                           uint32_t baseH, uint32_t baseL, uint32_t sAdd) {
#pragma unroll
    for (int j = 0; j < 4; j++) {
        uint32_t bh0, bh1, bh2, bh3, bl0, bl1, bl2, bl3;
        LDSM4(bh0, bh1, bh2, bh3, baseH + j * 4096 + sAdd);
        LDSM4(bl0, bl1, bl2, bl3, baseL + j * 4096 + sAdd);
        MMA(c[2 * j][0], c[2 * j][1], c[2 * j][2], c[2 * j][3],
            aH[0], aH[1], aH[2], aH[3], bh0, bh1);
        MMA(c[2 * j + 1][0], c[2 * j + 1][1], c[2 * j + 1][2], c[2 * j + 1][3],
            aH[0], aH[1], aH[2], aH[3], bh2, bh3);
        MMA(c[2 * j][0], c[2 * j][1], c[2 * j][2], c[2 * j][3],
            aH[0], aH[1], aH[2], aH[3], bl0, bl1);
        MMA(c[2 * j + 1][0], c[2 * j + 1][1], c[2 * j + 1][2], c[2 * j + 1][3],
            aH[0], aH[1], aH[2], aH[3], bl2, bl3);
        MMA(c[2 * j][0], c[2 * j][1], c[2 * j][2], c[2 * j][3],
            aL[0], aL[1], aL[2], aL[3], bh0, bh1);
        MMA(c[2 * j + 1][0], c[2 * j + 1][1], c[2 * j + 1][2], c[2 * j + 1][3],
            aL[0], aL[1], aL[2], aL[3], bh2, bh3);
    }
}

// A fragments (16 rows x k16) straight from a global fp32 row pointer, hi/lo split
__device__ __forceinline__ void load_a_frags(const float* arow, int s,
                                             uint32_t (&aH)[4], uint32_t (&aL)[4]) {
    float2 v00 = *(const float2*)(arow + 16 * s);
    float2 v10 = *(const float2*)(arow + 16 * s + 8 * D);
    float2 v01 = *(const float2*)(arow + 16 * s + 8);
    float2 v11 = *(const float2*)(arow + 16 * s + 8 * D + 8);
    split2(v00.x, v00.y, aH[0], aL[0]);
    split2(v10.x, v10.y, aH[1], aL[1]);
    split2(v01.x, v01.y, aH[2], aL[2]);
    split2(v11.x, v11.y, aH[3], aL[3]);
}

// Store one fp32 value into a hi/lo bf16 B-image ([n][k] layout, XOR swizzle) at (k=m, n).
__device__ __forceinline__ void store_bimg(char* smem, uint32_t dH, uint32_t dL,
                                           int m, int n, float v) {
    uint32_t off = ((uint32_t)(n * 256 + m * 2)) ^ (((uint32_t)n & 7u) << 4);
    __nv_bfloat16 h = __float2bfloat16(v);
    *(__nv_bfloat16*)(smem + dH + off) = h;
    *(__nv_bfloat16*)(smem + dL + off) = __float2bfloat16(v - __bfloat162float(h));
}

// ===================== single fused kernel =====================
__global__ void __launch_bounds__(NTHREADS, 1)
lgn_main(const float* __restrict__ x, const float* __restrict__ graph,
         const float* __restrict__ W_msg, const float* __restrict__ b_msg,
         const float* __restrict__ W_upd, const float* __restrict__ b_upd,
         const float* __restrict__ Wout, const float* __restrict__ bout,
         const float* __restrict__ gamma, const float* __restrict__ beta,
         float* __restrict__ out) {
    extern __shared__ char smem[];
    const uint32_t sb = smem_u32(smem);
    const int tid = threadIdx.x;
    const int wid = tid >> 5;
    const int l = tid & 31;
    const int pair = wid >> 1;     // 0..7: owns rows [16*pair, 16*pair+16)
    const int half = wid & 1;      // 0: cols 0-63, 1: cols 64-127
    const int quad = l >> 2;
    const int qid = l & 3;
    const int mA = pair * 16 + quad;
    const int mB = mA + 8;
    const int nh = half * 64;

    // B-image ldmatrix lane constants
    const uint32_t nlane = ((l >> 4) & 1) * 8 + (l & 7);
    const uint32_t laneN = nlane * 256;
    const uint32_t xorv  = (nlane & 7) << 4;
    const uint32_t kl2   = ((l >> 3) & 1) * 16;
    const uint32_t bhl   = (uint32_t)half * 16384 + laneN;   // half col offset + lane row

    // h-staging (A-image) lane constants
    const uint32_t arow  = (l & 7) + ((l >> 3) & 1) * 8;
    const uint32_t akadd = ((l >> 4) & 1) * 16;
    const uint32_t axor  = (l & 7) << 4;
    const uint32_t shpH  = sb + SHH + pair * 4096 + arow * 256;
    const uint32_t shpL  = sb + SHL + pair * 4096 + arow * 256;
    char* hwH = smem + SHH + pair * 4096;   // write side (by row)
    char* hwL = smem + SHL + pair * 4096;
    const int barid = pair + 1;

    // =========================================================================
    // In-kernel precompute:
    //   T1 = graph @ W_upd[128:], W1 = W_upd[:128] + W_msg @ T1
    //   bg = b_msg @ graph,       b1 = b_upd + bg @ W_upd[128:]
    // =========================================================================

    // ---- P0: stage Wb = W_upd[128:] as B image into SW1; bg quarter sums ----
    for (int idx = tid; idx < D * D; idx += NTHREADS) {
        int k = idx >> 7, n = idx & 127;
        store_bimg(smem, SW1H, SW1L, k, n, W_upd[(D + k) * D + n]);
    }
    {
        int j = tid & 127, hh = tid >> 7;   // hh in 0..3
        float p = 0.f;
#pragma unroll 8
        for (int g = hh * 32; g < hh * 32 + 32; g++)
            p += b_msg[g] * graph[g * D + j];
        ((float*)(smem + SRED))[tid] = p;
    }
    __syncthreads();
    if (tid < D) {
        const float* sr = (const float*)(smem + SRED);
        ((float*)(smem + SGAM))[tid] = sr[tid] + sr[tid + 128] + sr[tid + 256] + sr[tid + 384];
    }

    // ---- P1: T1 = graph @ Wb ; write T1^T -> SW2 B-image ----
    {
        float c[8][4];
#pragma unroll
        for (int j = 0; j < 8; j++) { c[j][0] = c[j][1] = c[j][2] = c[j][3] = 0.f; }
        const float* ar = graph + (size_t)mA * D + qid * 2;
#pragma unroll
        for (int s = 0; s < 8; s++) {
            uint32_t aH[4], aL[4];
            load_a_frags(ar, s, aH, aL);
            pair_kstep(c, aH, aL, sb + SW1H, sb + SW1L, bhl + (((uint32_t)(32 * s) + kl2) ^ xorv));
        }
#pragma unroll
        for (int j = 0; j < 8; j++) {
            int n0 = nh + 8 * j + qid * 2;
            store_bimg(smem, SW2H, SW2L, mA, n0,     c[j][0]);
            store_bimg(smem, SW2H, SW2L, mA, n0 + 1, c[j][1]);
            store_bimg(smem, SW2H, SW2L, mB, n0,     c[j][2]);
            store_bimg(smem, SW2H, SW2L, mB, n0 + 1, c[j][3]);
        }
    }
    __syncthreads();

    // ---- P2: W1 = W_upd[:128] + W_msg @ T1 ; write -> SW1 B-image ----
    {
        float c[8][4];
#pragma unroll
        for (int j = 0; j < 8; j++) { c[j][0] = c[j][1] = c[j][2] = c[j][3] = 0.f; }
        const float* ar = W_msg + (size_t)mA * D + qid * 2;
#pragma unroll
        for (int s = 0; s < 8; s++) {
            uint32_t aH[4], aL[4];
            load_a_frags(ar, s, aH, aL);
            pair_kstep(c, aH, aL, sb + SW2H, sb + SW2L, bhl + (((uint32_t)(32 * s) + kl2) ^ xorv));
        }
#pragma unroll
        for (int j = 0; j < 8; j++) {
            int n0 = nh + 8 * j + qid * 2;
            float2 tA = *(const float2*)(W_upd + (size_t)mA * D + n0);
            float2 tB = *(const float2*)(W_upd + (size_t)mB * D + n0);
            c[j][0] += tA.x; c[j][1] += tA.y; c[j][2] += tB.x; c[j][3] += tB.y;
        }
        // SW1 (Wb) dead after P1's sync -> safe to overwrite
#pragma unroll
        for (int j = 0; j < 8; j++) {
            int n0 = nh + 8 * j + qid * 2;
            store_bimg(smem, SW1H, SW1L, mA, n0,     c[j][0]);
            store_bimg(smem, SW1H, SW1L, mA, n0 + 1, c[j][1]);
            store_bimg(smem, SW1H, SW1L, mB, n0,     c[j][2]);
            store_bimg(smem, SW1H, SW1L, mB, n0 + 1, c[j][3]);
        }
    }
    __syncthreads();

    // ---- P3: stage W_out -> SW2 (T1 dead); b1 from bg; final vectors ----
    for (int idx = tid; idx < D * D; idx += NTHREADS) {
        int k = idx >> 7, n = idx & 127;
        store_bimg(smem, SW2H, SW2L, k, n, Wout[k * D + n]);
    }
    if (tid < D) {
        const float* bgv = (const float*)(smem + SGAM);
        float acc = b_upd[tid];
#pragma unroll 8
        for (int h = 0; h < D; h++)
            acc += bgv[h] * W_upd[(D + h) * D + tid];
        ((float*)(smem + SB1))[tid] = acc;
    }
    __syncthreads();
    if (tid < D) {
        ((float*)(smem + SB2))[tid]  = bout[tid];
        ((float*)(smem + SGAM))[tid] = gamma[tid];
        ((float*)(smem + SBET))[tid] = beta[tid];
    }
    __syncthreads();

    const float* b1s = (const float*)(smem + SB1);
    const float* b2s = (const float*)(smem + SB2);
    const float* gms = (const float*)(smem + SGAM);
    const float* bts = (const float*)(smem + SBET);

    // =========================================================================
    // Main loop: per 128-row tile:  y = LN( gelu(x@W1 + b1) @ W2 + b2 )
    // =========================================================================
    for (int t = blockIdx.x; t < NTILES; t += gridDim.x) {
        const float* xrow = x + (size_t)t * (128 * D) + (size_t)mA * D + qid * 2;

        // ---- GEMM1: C1 = x @ W1 + b1  (warp's 64-col half) ----
        float c1[8][4];
#pragma unroll
        for (int j = 0; j < 8; j++) {
            float2 bb = *(const float2*)(b1s + nh + 8 * j + qid * 2);
            c1[j][0] = bb.x; c1[j][1] = bb.y; c1[j][2] = bb.x; c1[j][3] = bb.y;
        }
#pragma unroll
        for (int s = 0; s < 8; s++) {
            uint32_t aH[4], aL[4];
            load_a_frags(xrow, s, aH, aL);
            pair_kstep(c1, aH, aL, sb + SW1H, sb + SW1L, bhl + (((uint32_t)(32 * s) + kl2) ^ xorv));
        }

        // ---- epilogue 1: exact GELU, split, stage h (warp's k-half) to pair SMEM ----
#pragma unroll
        for (int j = 0; j < 8; j++) {
            uint32_t kb = (uint32_t)(half * 128 + 16 * j + 4 * qid);
            float v0 = gelu_exact(c1[j][0]);
            float v1 = gelu_exact(c1[j][1]);
            float v2 = gelu_exact(c1[j][2]);
            float v3 = gelu_exact(c1[j][3]);
            uint32_t hA, lA, hB, lB;
            split2(v0, v1, hA, lA);
            split2(v2, v3, hB, lB);
            uint32_t oA = (uint32_t)quad * 256 + (kb ^ ((uint32_t)quad << 4));
            uint32_t oB = (uint32_t)(quad + 8) * 256 + (kb ^ ((uint32_t)quad << 4));
            *(uint32_t*)(hwH + oA) = hA;
            *(uint32_t*)(hwL + oA) = lA;
            *(uint32_t*)(hwH + oB) = hB;
            *(uint32_t*)(hwL + oB) = lB;
        }
        BARP(barid);   // pair: h staging complete (bar.sync drains STS)

        // ---- GEMM2: C2 = h @ W_out + b_out ----
        float c2[8][4];
#pragma unroll
        for (int j = 0; j < 8; j++) {
            float2 bb = *(const float2*)(b2s + nh + 8 * j + qid * 2);
            c2[j][0] = bb.x; c2[j][1] = bb.y; c2[j][2] = bb.x; c2[j][3] = bb.y;
        }
#pragma unroll
        for (int s = 0; s < 8; s++) {
            uint32_t ao = ((uint32_t)(32 * s) + akadd) ^ axor;
            uint32_t aH[4], aL[4];
            LDSM4(aH[0], aH[1], aH[2], aH[3], shpH + ao);
            LDSM4(aL[0], aL[1], aL[2], aL[3], shpL + ao);
            pair_kstep(c2, aH, aL, sb + SW2H, sb + SW2L, bhl + (((uint32_t)(32 * s) + kl2) ^ xorv));
        }

        // ---- epilogue 2: LayerNorm (quad bfly + pair exchange) + store ----
        float sA = 0.f, qA = 0.f, sB = 0.f, qB = 0.f;
#pragma unroll
        for (int j = 0; j < 8; j++) {
            sA += c2[j][0] + c2[j][1];
            qA += c2[j][0] * c2[j][0] + c2[j][1] * c2[j][1];
            sB += c2[j][2] + c2[j][3];
            qB += c2[j][2] * c2[j][2] + c2[j][3] * c2[j][3];
        }
#pragma unroll
        for (int m = 1; m < 4; m <<= 1) {
            sA += __shfl_xor_sync(0xFFFFFFFFu, sA, m);
            qA += __shfl_xor_sync(0xFFFFFFFFu, qA, m);
            sB += __shfl_xor_sync(0xFFFFFFFFu, sB, m);
            qB += __shfl_xor_sync(0xFFFFFFFFu, qB, m);
        }
        if (qid == 0) {
            *(float4*)(smem + SRED + pair * 256 + half * 128 + quad * 16) =
                make_float4(sA, qA, sB, qB);
        }
        BARP(barid);   // pair: partials visible; also fences h reads before next overwrite
        {
            float4 o = *(const float4*)(smem + SRED + pair * 256 + (half ^ 1) * 128 + quad * 16);
            sA += o.x; qA += o.y; sB += o.z; qB += o.w;
        }
        float mnA = sA * (1.0f / 128.0f);
        float iA = rsqrtf(qA * (1.0f / 128.0f) - mnA * mnA + 1e-5f);
        float mnB = sB * (1.0f / 128.0f);
        float iB = rsqrtf(qB * (1.0f / 128.0f) - mnB * mnB + 1e-5f);

        float* oA = out + (size_t)t * (128 * D) + (size_t)mA * D;
        float* oB = out + (size_t)t * (128 * D) + (size_t)mB * D;
#pragma unroll
        for (int j = 0; j < 8; j++) {
            int n0 = nh + 8 * j + qid * 2;
            float2 g = *(const float2*)(gms + n0);
            float2 b = *(const float2*)(bts + n0);
            float2 rA, rB;
            rA.x = (c2[j][0] - mnA) * iA * g.x + b.x;
            rA.y = (c2[j][1] - mnA) * iA * g.y + b.y;
            rB.x = (c2[j][2] - mnB) * iB * g.x + b.x;
            rB.y = (c2[j][3] - mnB) * iB * g.y + b.y;
            *(float2*)(oA + n0) = rA;
            *(float2*)(oB + n0) = rB;
        }
    }
}

// ===================== launch (single kernel per call) =====================
extern "C" void kernel_launch(void* const* d_in, const int* in_sizes, int n_in,
                              void* d_out, int out_size) {
    const float* x     = (const float*)d_in[0];
    const float* graph = (const float*)d_in[1];
    const float* W_msg = (const float*)d_in[2];
    const float* b_msg = (const float*)d_in[3];
    const float* W_upd = (const float*)d_in[4];
    const float* b_upd = (const float*)d_in[5];
    const float* W_out = (const float*)d_in[6];
    const float* b_out = (const float*)d_in[7];
    const float* gamma = (const float*)d_in[8];
    const float* beta  = (const float*)d_in[9];
    float* out = (float*)d_out;

    cudaFuncSetAttribute(lgn_main, cudaFuncAttributeMaxDynamicSharedMemorySize, SMEM_BYTES);

    lgn_main<<<GRID_MAIN, NTHREADS, SMEM_BYTES>>>(
        x, graph, W_msg, b_msg, W_upd, b_upd, W_out, b_out, gamma, beta, out);
}

// round 11
// speedup vs baseline: 1.3470x; 1.2074x over previous
#include <cuda_runtime.h>
#include <cuda_fp16.h>
#include <cstdint>
#include <math.h>

// ===================== problem constants =====================
#define D 128
#define NROWS (64 * 4096)          // B*T = 262144
#define NTILES (NROWS / 128)       // 2048
#define GRID_MAIN 148
#define NTHREADS 512               // 16 warps = 8 pairs; pair owns 16 rows, warp owns 64 cols

// ===================== helpers =====================
__device__ __forceinline__ uint32_t smem_u32(const void* p) {
    uint32_t a;
    asm("{ .reg .u64 t; cvta.to.shared.u64 t, %1; cvt.u32.u64 %0, t; }" : "=r"(a) : "l"(p));
    return a;
}
__device__ __forceinline__ uint32_t pack2h(__half a, __half b) {
    return (uint32_t)__half_as_ushort(a) | ((uint32_t)__half_as_ushort(b) << 16);
}
// fp16 two-term split: x = hi + lo (hi RN, lo captures ~11 extra mantissa bits)
__device__ __forceinline__ void split2h(float x0, float x1, uint32_t& hi, uint32_t& lo) {
    __half h0 = __float2half_rn(x0), h1 = __float2half_rn(x1);
    hi = pack2h(h0, h1);
    lo = pack2h(__float2half_rn(x0 - __half2float(h0)),
                __float2half_rn(x1 - __half2float(h1)));
}
__device__ __forceinline__ float gelu_exact(float v) {
    return 0.5f * v * (1.0f + erff(v * 0.70710678118654752f));
}

// mma.sync m16n8k16 fp16 -> f32, accumulate in place
#define MMA(c0, c1, c2, c3, a0, a1, a2, a3, b0, b1)                                   \
    asm volatile("mma.sync.aligned.m16n8k16.row.col.f32.f16.f16.f32 "                 \
                 "{%0,%1,%2,%3}, {%4,%5,%6,%7}, {%8,%9}, {%0,%1,%2,%3};"              \
                 : "+f"(c0), "+f"(c1), "+f"(c2), "+f"(c3)                             \
                 : "r"(a0), "r"(a1), "r"(a2), "r"(a3), "r"(b0), "r"(b1))

#define LDSM4(r0, r1, r2, r3, addr)                                                    \
    asm volatile("ldmatrix.sync.aligned.m8n8.x4.shared.b16 {%0,%1,%2,%3}, [%4];"       \
                 : "=r"(r0), "=r"(r1), "=r"(r2), "=r"(r3) : "r"(addr))

// named barrier for a 64-thread pair (ids 1..8)
#define BARP(id) asm volatile("bar.sync %0, 64;" :: "r"(id) : "memory")

// ===================== SMEM map =====================
// Weight images: [n][k] fp16, 256B rows, XOR-swizzled 16B chunks (conflict-free ldmatrix)
#define SW1  0          // W1 image (32 KB); Wb during precompute
#define SW2  32768      // W_out image (32 KB); T1 during precompute
#define SHH  65536      // h staging hi: 8 pairs * 4 KB (16 rows x 256B, A layout)
#define SHL  98304      // h staging lo
#define SB1  131072     // b1
#define SB2  131584     // b_out
#define SGAM 132096     // gamma (bg during precompute)
#define SBET 132608     // beta
#define SRED 133120     // 2 KB: LN pair partials / bg scratch
#define SMEM_BYTES 135168

// One k-step (K=16) of a 16x64 half-warp GEMM, 2-term fp16 (A split, B single).
// c[8][4] covers 16 rows x 64 cols. sAdd includes half*16384 + laneN + swizzled k.
__device__ __forceinline__ void pair_kstep(float (&c)[8][4],
                                           const uint32_t* aH, const uint32_t* aL,
                                           uint32_t base, uint32_t sAdd) {
#pragma unroll
    for (int j = 0; j < 4; j++) {
        uint32_t b0, b1, b2, b3;
        LDSM4(b0, b1, b2, b3, base + j * 4096 + sAdd);
        MMA(c[2 * j][0], c[2 * j][1], c[2 * j][2], c[2 * j][3],
            aH[0], aH[1], aH[2], aH[3], b0, b1);
        MMA(c[2 * j + 1][0], c[2 * j + 1][1], c[2 * j + 1][2], c[2 * j + 1][3],
            aH[0], aH[1], aH[2], aH[3], b2, b3);
        MMA(c[2 * j][0], c[2 * j][1], c[2 * j][2], c[2 * j][3],
            aL[0], aL[1], aL[2], aL[3], b0, b1);
        MMA(c[2 * j + 1][0], c[2 * j + 1][1], c[2 * j + 1][2], c[2 * j + 1][3],
            aL[0], aL[1], aL[2], aL[3], b2, b3);
    }
}

// A fragments (16 rows x k16) straight from a global fp32 row pointer, fp16 hi/lo split
__device__ __forceinline__ void load_a_frags(const float* arow, int s,
                                             uint32_t (&aH)[4], uint32_t (&aL)[4]) {
    float2 v00 = *(const float2*)(arow + 16 * s);
    float2 v10 = *(const float2*)(arow + 16 * s + 8 * D);
    float2 v01 = *(const float2*)(arow + 16 * s + 8);
    float2 v11 = *(const float2*)(arow + 16 * s + 8 * D + 8);
    split2h(v00.x, v00.y, aH[0], aL[0]);
    split2h(v10.x, v10.y, aH[1], aL[1]);
    split2h(v01.x, v01.y, aH[2], aL[2]);
    split2h(v11.x, v11.y, aH[3], aL[3]);
}

// Store one fp32 value into a single-fp16 B-image ([n][k] layout, XOR swizzle) at (k=m, n).
__device__ __forceinline__ void store_bimg(char* smem, uint32_t dst, int m, int n, float v) {
    uint32_t off = ((uint32_t)(n * 256 + m * 2)) ^ (((uint32_t)n & 7u) << 4);
    *(__half*)(smem + dst + off) = __float2half_rn(v);
}

// ===================== single fused kernel =====================
__global__ void __launch_bounds__(NTHREADS, 1)
lgn_main(const float* __restrict__ x, const float* __restrict__ graph,
         const float* __restrict__ W_msg, const float* __restrict__ b_msg,
         const float* __restrict__ W_upd, const float* __restrict__ b_upd,
         const float* __restrict__ Wout, const float* __restrict__ bout,
         const float* __restrict__ gamma, const float* __restrict__ beta,
         float* __restrict__ out) {
    extern __shared__ char smem[];
    const uint32_t sb = smem_u32(smem);
    const int tid = threadIdx.x;
    const int wid = tid >> 5;
    const int l = tid & 31;
    const int pair = wid >> 1;     // 0..7: owns rows [16*pair, 16*pair+16)
    const int half = wid & 1;      // 0: cols 0-63, 1: cols 64-127
    const int quad = l >> 2;
    const int qid = l & 3;
    const int mA = pair * 16 + quad;
    const int mB = mA + 8;
    const int nh = half * 64;

    // B-image ldmatrix lane constants
    const uint32_t nlane = ((l >> 4) & 1) * 8 + (l & 7);
    const uint32_t laneN = nlane * 256;
    const uint32_t xorv  = (nlane & 7) << 4;
    const uint32_t kl2   = ((l >> 3) & 1) * 16;
    const uint32_t bhl   = (uint32_t)half * 16384 + laneN;   // half col offset + lane row

    // h-staging (A-image) lane constants
    const uint32_t arow  = (l & 7) + ((l >> 3) & 1) * 8;
    const uint32_t akadd = ((l >> 4) & 1) * 16;
    const uint32_t axor  = (l & 7) << 4;
    const uint32_t shpH  = sb + SHH + pair * 4096 + arow * 256;
    const uint32_t shpL  = sb + SHL + pair * 4096 + arow * 256;
    char* hwH = smem + SHH + pair * 4096;   // write side (by row)
    char* hwL = smem + SHL + pair * 4096;
    const int barid = pair + 1;

    // =========================================================================
    // In-kernel precompute:
    //   T1 = graph @ W_upd[128:], W1 = W_upd[:128] + W_msg @ T1
    //   bg = b_msg @ graph,       b1 = b_upd + bg @ W_upd[128:]
    // =========================================================================

    // ---- P0: stage Wb = W_upd[128:] as B image into SW1; bg quarter sums ----
    for (int idx = tid; idx < D * D; idx += NTHREADS) {
        int k = idx >> 7, n = idx & 127;
        store_bimg(smem, SW1, k, n, W_upd[(D + k) * D + n]);
    }
    {
        int j = tid & 127, hh = tid >> 7;   // hh in 0..3
        float p = 0.f;
#pragma unroll 8
        for (int g = hh * 32; g < hh * 32 + 32; g++)
            p += b_msg[g] * graph[g * D + j];
        ((float*)(smem + SRED))[tid] = p;
    }
    __syncthreads();
    if (tid < D) {
        const float* sr = (const float*)(smem + SRED);
        ((float*)(smem + SGAM))[tid] = sr[tid] + sr[tid + 128] + sr[tid + 256] + sr[tid + 384];
    }

    // ---- P1: T1 = graph @ Wb ; write T1^T -> SW2 B-image ----
    {
        float c[8][4];
#pragma unroll
        for (int j = 0; j < 8; j++) { c[j][0] = c[j][1] = c[j][2] = c[j][3] = 0.f; }
        const float* ar = graph + (size_t)mA * D + qid * 2;
#pragma unroll
        for (int s = 0; s < 8; s++) {
            uint32_t aH[4], aL[4];
            load_a_frags(ar, s, aH, aL);
            pair_kstep(c, aH, aL, sb + SW1, bhl + (((uint32_t)(32 * s) + kl2) ^ xorv));
        }
#pragma unroll
        for (int j = 0; j < 8; j++) {
            int n0 = nh + 8 * j + qid * 2;
            store_bimg(smem, SW2, mA, n0,     c[j][0]);
            store_bimg(smem, SW2, mA, n0 + 1, c[j][1]);
            store_bimg(smem, SW2, mB, n0,     c[j][2]);
            store_bimg(smem, SW2, mB, n0 + 1, c[j][3]);
        }
    }
    __syncthreads();

    // ---- P2: W1 = W_upd[:128] + W_msg @ T1 ; write -> SW1 B-image ----
    {
        float c[8][4];
#pragma unroll
        for (int j = 0; j < 8; j++) { c[j][0] = c[j][1] = c[j][2] = c[j][3] = 0.f; }
        const float* ar = W_msg + (size_t)mA * D + qid * 2;
#pragma unroll
        for (int s = 0; s < 8; s++) {
            uint32_t aH[4], aL[4];
            load_a_frags(ar, s, aH, aL);
            pair_kstep(c, aH, aL, sb + SW2, bhl + (((uint32_t)(32 * s) + kl2) ^ xorv));
        }
#pragma unroll
        for (int j = 0; j < 8; j++) {   // += W_upd top half
            int n0 = nh + 8 * j + qid * 2;
            float2 tA = *(const float2*)(W_upd + (size_t)mA * D + n0);
            float2 tB = *(const float2*)(W_upd + (size_t)mB * D + n0);
            c[j][0] += tA.x; c[j][1] += tA.y; c[j][2] += tB.x; c[j][3] += tB.y;
        }
        // SW1 (Wb) dead after P1's sync -> safe to overwrite
#pragma unroll
        for (int j = 0; j < 8; j++) {
            int n0 = nh + 8 * j + qid * 2;
            store_bimg(smem, SW1, mA, n0,     c[j][0]);
            store_bimg(smem, SW1, mA, n0 + 1, c[j][1]);
            store_bimg(smem, SW1, mB, n0,     c[j][2]);
            store_bimg(smem, SW1, mB, n0 + 1, c[j][3]);
        }
    }
    __syncthreads();

    // ---- P3: stage W_out -> SW2 (T1 dead); b1 from bg; final vectors ----
    for (int idx = tid; idx < D * D; idx += NTHREADS) {
        int k = idx >> 7, n = idx & 127;
        store_bimg(smem, SW2, k, n, Wout[k * D + n]);
    }
    if (tid < D) {
        const float* bgv = (const float*)(smem + SGAM);
        float acc = b_upd[tid];
#pragma unroll 8
        for (int h = 0; h < D; h++)
            acc += bgv[h] * W_upd[(D + h) * D + tid];
        ((float*)(smem + SB1))[tid] = acc;
    }
    __syncthreads();
    if (tid < D) {
        ((float*)(smem + SB2))[tid]  = bout[tid];
        ((float*)(smem + SGAM))[tid] = gamma[tid];
        ((float*)(smem + SBET))[tid] = beta[tid];
    }
    __syncthreads();

    const float* b1s = (const float*)(smem + SB1);
    const float* b2s = (const float*)(smem + SB2);
    const float* gms = (const float*)(smem + SGAM);
    const float* bts = (const float*)(smem + SBET);

    // =========================================================================
    // Main loop: per 128-row tile:  y = LN( gelu(x@W1 + b1) @ W2 + b2 )
    // =========================================================================
    for (int t = blockIdx.x; t < NTILES; t += gridDim.x) {
        const float* xrow = x + (size_t)t * (128 * D) + (size_t)mA * D + qid * 2;

        // ---- GEMM1: C1 = x @ W1 + b1  (warp's 64-col half) ----
        float c1[8][4];
#pragma unroll
        for (int j = 0; j < 8; j++) {
            float2 bb = *(const float2*)(b1s + nh + 8 * j + qid * 2);
            c1[j][0] = bb.x; c1[j][1] = bb.y; c1[j][2] = bb.x; c1[j][3] = bb.y;
        }
#pragma unroll
        for (int s = 0; s < 8; s++) {
            uint32_t aH[4], aL[4];
            load_a_frags(xrow, s, aH, aL);
            pair_kstep(c1, aH, aL, sb + SW1, bhl + (((uint32_t)(32 * s) + kl2) ^ xorv));
        }

        // ---- epilogue 1: exact GELU, fp16 split, stage h (warp's k-half) to pair SMEM ----
#pragma unroll
        for (int j = 0; j < 8; j++) {
            uint32_t kb = (uint32_t)(half * 128 + 16 * j + 4 * qid);
            float v0 = gelu_exact(c1[j][0]);
            float v1 = gelu_exact(c1[j][1]);
            float v2 = gelu_exact(c1[j][2]);
            float v3 = gelu_exact(c1[j][3]);
            uint32_t hA, lA, hB, lB;
            split2h(v0, v1, hA, lA);
            split2h(v2, v3, hB, lB);
            uint32_t oA = (uint32_t)quad * 256 + (kb ^ ((uint32_t)quad << 4));
            uint32_t oB = (uint32_t)(quad + 8) * 256 + (kb ^ ((uint32_t)quad << 4));
            *(uint32_t*)(hwH + oA) = hA;
            *(uint32_t*)(hwL + oA) = lA;
            *(uint32_t*)(hwH + oB) = hB;
            *(uint32_t*)(hwL + oB) = lB;
        }
        BARP(barid);   // pair: h staging complete (bar.sync drains STS)

        // ---- GEMM2: C2 = h @ W_out + b_out ----
        float c2[8][4];
#pragma unroll
        for (int j = 0; j < 8; j++) {
            float2 bb = *(const float2*)(b2s + nh + 8 * j + qid * 2);
            c2[j][0] = bb.x; c2[j][1] = bb.y; c2[j][2] = bb.x; c2[j][3] = bb.y;
        }
#pragma unroll
        for (int s = 0; s < 8; s++) {
            uint32_t ao = ((uint32_t)(32 * s) + akadd) ^ axor;
            uint32_t aH[4], aL[4];
            LDSM4(aH[0], aH[1], aH[2], aH[3], shpH + ao);
            LDSM4(aL[0], aL[1], aL[2], aL[3], shpL + ao);
            pair_kstep(c2, aH, aL, sb + SW2, bhl + (((uint32_t)(32 * s) + kl2) ^ xorv));
        }

        // ---- epilogue 2: LayerNorm (quad bfly + pair exchange) + store ----
        float sA = 0.f, qA = 0.f, sB = 0.f, qB = 0.f;
#pragma unroll
        for (int j = 0; j < 8; j++) {
            sA += c2[j][0] + c2[j][1];
            qA += c2[j][0] * c2[j][0] + c2[j][1] * c2[j][1];
            sB += c2[j][2] + c2[j][3];
            qB += c2[j][2] * c2[j][2] + c2[j][3] * c2[j][3];
        }
#pragma unroll
        for (int m = 1; m < 4; m <<= 1) {
            sA += __shfl_xor_sync(0xFFFFFFFFu, sA, m);
            qA += __shfl_xor_sync(0xFFFFFFFFu, qA, m);
            sB += __shfl_xor_sync(0xFFFFFFFFu, sB, m);
            qB += __shfl_xor_sync(0xFFFFFFFFu, qB, m);
        }
        if (qid == 0) {
            *(float4*)(smem + SRED + pair * 256 + half * 128 + quad * 16) =
                make_float4(sA, qA, sB, qB);
        }
        BARP(barid);   // pair: partials visible; also fences h reads before next overwrite
        {
            float4 o = *(const float4*)(smem + SRED + pair * 256 + (half ^ 1) * 128 + quad * 16);
            sA += o.x; qA += o.y; sB += o.z; qB += o.w;
        }
        float mnA = sA * (1.0f / 128.0f);
        float iA = rsqrtf(qA * (1.0f / 128.0f) - mnA * mnA + 1e-5f);
        float mnB = sB * (1.0f / 128.0f);
        float iB = rsqrtf(qB * (1.0f / 128.0f) - mnB * mnB + 1e-5f);

        float* oA = out + (size_t)t * (128 * D) + (size_t)mA * D;
        float* oB = out + (size_t)t * (128 * D) + (size_t)mB * D;
#pragma unroll
        for (int j = 0; j < 8; j++) {
            int n0 = nh + 8 * j + qid * 2;
            float2 g = *(const float2*)(gms + n0);
            float2 b = *(const float2*)(bts + n0);
            float2 rA, rB;
            rA.x = (c2[j][0] - mnA) * iA * g.x + b.x;
            rA.y = (c2[j][1] - mnA) * iA * g.y + b.y;
            rB.x = (c2[j][2] - mnB) * iB * g.x + b.x;
            rB.y = (c2[j][3] - mnB) * iB * g.y + b.y;
            *(float2*)(oA + n0) = rA;
            *(float2*)(oB + n0) = rB;
        }
    }
}

// ===================== launch (single kernel per call) =====================
extern "C" void kernel_launch(void* const* d_in, const int* in_sizes, int n_in,
                              void* d_out, int out_size) {
    const float* x     = (const float*)d_in[0];
    const float* graph = (const float*)d_in[1];
    const float* W_msg = (const float*)d_in[2];
    const float* b_msg = (const float*)d_in[3];
    const float* W_upd = (const float*)d_in[4];
    const float* b_upd = (const float*)d_in[5];
    const float* W_out = (const float*)d_in[6];
    const float* b_out = (const float*)d_in[7];
    const float* gamma = (const float*)d_in[8];
    const float* beta  = (const float*)d_in[9];
    float* out = (float*)d_out;

    cudaFuncSetAttribute(lgn_main, cudaFuncAttributeMaxDynamicSharedMemorySize, SMEM_BYTES);

    lgn_main<<<GRID_MAIN, NTHREADS, SMEM_BYTES>>>(
        x, graph, W_msg, b_msg, W_upd, b_upd, W_out, b_out, gamma, beta, out);
}